// round 12
// baseline (speedup 1.0000x reference)
#include <cuda_runtime.h>
#include <cuda_fp16.h>
#include <cstdint>

#define NB 8
#define NL 256
#define NF 6272
#define NU 32
#define KSPLIT 28

// Scratch (no cudaMalloc allowed)
__device__ float g_p[NB*NL*NU];                      // projections (atomic-accumulated)
__device__ __half g_af[NB*NL*NL];                    // a (softmax) fp16 [b][q][k]
__device__ __half g_xh[(size_t)NB*NL*NF];            // inputs fp16 [b][k][f] (written by k_proj)

// ---------------------------------------------------------------------------
// helpers
// ---------------------------------------------------------------------------
__device__ __forceinline__ uint32_t s2u(const void* p){
    uint32_t a;
    asm("{ .reg .u64 t; cvta.to.shared.u64 t, %1; cvt.u32.u64 %0, t; }" : "=r"(a) : "l"(p));
    return a;
}
__device__ __forceinline__ float tanh_approx(float x){
    float y; asm("tanh.approx.f32 %0, %1;" : "=f"(y) : "f"(x)); return y;
}
__device__ __forceinline__ void ldsm4(uint32_t r[4], uint32_t a){
    asm volatile("ldmatrix.sync.aligned.m8n8.x4.shared.b16 {%0,%1,%2,%3}, [%4];"
                 : "=r"(r[0]), "=r"(r[1]), "=r"(r[2]), "=r"(r[3]) : "r"(a));
}
__device__ __forceinline__ void ldsm4t(uint32_t r[4], uint32_t a){
    asm volatile("ldmatrix.sync.aligned.m8n8.x4.trans.shared.b16 {%0,%1,%2,%3}, [%4];"
                 : "=r"(r[0]), "=r"(r[1]), "=r"(r[2]), "=r"(r[3]) : "r"(a));
}
__device__ __forceinline__ void mma_f16(float c[4], const uint32_t a[4], uint32_t b0, uint32_t b1){
    asm volatile(
        "mma.sync.aligned.m16n8k16.row.col.f32.f16.f16.f32 "
        "{%0,%1,%2,%3}, {%4,%5,%6,%7}, {%8,%9}, {%0,%1,%2,%3};"
        : "+f"(c[0]), "+f"(c[1]), "+f"(c[2]), "+f"(c[3])
        : "r"(a[0]), "r"(a[1]), "r"(a[2]), "r"(a[3]), "r"(b0), "r"(b1));
}
// fp16 accumulator variant (presumed full-rate on sm_103 legacy tensor path)
__device__ __forceinline__ void mma_f16acc(uint32_t d[2], const uint32_t a[4],
                                           uint32_t b0, uint32_t b1){
    asm volatile(
        "mma.sync.aligned.m16n8k16.row.col.f16.f16.f16.f16 "
        "{%0,%1}, {%2,%3,%4,%5}, {%6,%7}, {%0,%1};"
        : "+r"(d[0]), "+r"(d[1])
        : "r"(a[0]), "r"(a[1]), "r"(a[2]), "r"(a[3]), "r"(b0), "r"(b1));
}
__device__ __forceinline__ uint2 cvt4h(float4 v){
    __half h[4];
    h[0] = __float2half(v.x); h[1] = __float2half(v.y);
    h[2] = __float2half(v.z); h[3] = __float2half(v.w);
    return *(uint2*)h;
}
__device__ __forceinline__ void cp16(uint32_t dst, const void* src){
    asm volatile("cp.async.cg.shared.global [%0], [%1], 16;" :: "r"(dst), "l"(src));
}
__device__ __forceinline__ void cp_commit(){ asm volatile("cp.async.commit_group;"); }
__device__ __forceinline__ void cp_wait1(){ asm volatile("cp.async.wait_group 1;"); }

// ---------------------------------------------------------------------------
// K_proj: g_p += x[rows, fchunk] @ Wt[fchunk, 32]  (fp16 HMMA, atomic partials)
// Also writes g_xh (inputs as fp16). grid (16, 28), 256 threads, f-chunk 224.
// ---------------------------------------------------------------------------
__global__ __launch_bounds__(256) void k_proj(const float* __restrict__ inp,
                                              const float* __restrict__ Wt){
    __shared__ __half Ah[128][40];
    __shared__ __half Bh[32][40];
    const int t = threadIdx.x, wid = t >> 5, l = t & 31;
    const int lr = l & 15, lc = (l >> 4) << 3;
    const int row0 = blockIdx.x * 128;
    const int fb0  = blockIdx.y * 224;

    const int arR[4] = { (t+0)>>3, (t+256)>>3, (t+512)>>3, (t+768)>>3 };
    const int arC    = (t & 7)*4;
    const int wrR    = t >> 3, wrC = (t & 7)*4;

    float acc[4][4];
    #pragma unroll
    for (int i = 0; i < 4; i++)
        #pragma unroll
        for (int j = 0; j < 4; j++) acc[i][j] = 0.f;

    const uint32_t a_ah = s2u(Ah), a_bh = s2u(Bh);

    float4 xv[4], wv;
    #pragma unroll
    for (int i = 0; i < 4; i++)
        xv[i] = *(const float4*)(inp + (size_t)(row0 + arR[i])*NF + fb0 + arC);
    wv = *(const float4*)(Wt + (size_t)(fb0 + wrR)*NU + wrC);

    for (int s = 0; s < 7; s++){
        const int fb = fb0 + s*32;
        #pragma unroll
        for (int i = 0; i < 4; i++){
            uint2 h = cvt4h(xv[i]);
            *(uint2*)&Ah[arR[i]][arC] = h;
            *(uint2*)&g_xh[(size_t)(row0 + arR[i])*NF + fb + arC] = h;
        }
        *(uint2*)&Bh[wrR][wrC] = cvt4h(wv);
        __syncthreads();

        if (s < 6){
            const int fbn = fb0 + (s+1)*32;
            #pragma unroll
            for (int i = 0; i < 4; i++)
                xv[i] = *(const float4*)(inp + (size_t)(row0 + arR[i])*NF + fbn + arC);
            wv = *(const float4*)(Wt + (size_t)(fbn + wrR)*NU + wrC);
        }

        #pragma unroll
        for (int ks = 0; ks < 32; ks += 16){
            uint32_t fa[4];
            ldsm4(fa, a_ah + ((wid*16 + lr)*40 + ks + lc)*2);
            uint32_t fb4[8];
            ldsm4t(fb4 + 0, a_bh + ((ks + lr)*40 + 0  + lc)*2);
            ldsm4t(fb4 + 4, a_bh + ((ks + lr)*40 + 16 + lc)*2);
            #pragma unroll
            for (int ng = 0; ng < 4; ng++)
                mma_f16(acc[ng], fa, fb4[ng*2], fb4[ng*2+1]);
        }
        __syncthreads();
    }
    const int r0 = row0 + wid*16 + (l >> 2);
    const int c0 = (l & 3)*2;
    #pragma unroll
    for (int ng = 0; ng < 4; ng++){
        atomicAdd(&g_p[(size_t)r0*NU + ng*8 + c0],     acc[ng][0]);
        atomicAdd(&g_p[(size_t)r0*NU + ng*8 + c0 + 1], acc[ng][1]);
        atomicAdd(&g_p[(size_t)(r0+8)*NU + ng*8 + c0],     acc[ng][2]);
        atomicAdd(&g_p[(size_t)(r0+8)*NU + ng*8 + c0 + 1], acc[ng][3]);
    }
}

// ---------------------------------------------------------------------------
// K_attn: block handles (b, 8 queries). grid (32, 8), 256 threads (t = k).
// ---------------------------------------------------------------------------
__global__ __launch_bounds__(256) void k_attn(const float* __restrict__ bh,
                                              const float* __restrict__ Wa,
                                              const float* __restrict__ ba){
    __shared__ float ps[NL][33];
    __shared__ float pqb[8][32];
    __shared__ float was[32];
    __shared__ float red[8][8];
    __shared__ float inv[8];

    const int t = threadIdx.x;
    const int b = blockIdx.y;
    const int q0 = blockIdx.x * 8;
    const float* pb = g_p + b*NL*NU;
    const float ba0 = ba[0];

    #pragma unroll
    for (int i = 0; i < 32; i++){
        int idx = t + i*256;
        ps[idx >> 5][idx & 31] = pb[idx];
    }
    if (t < 32) was[t] = Wa[t];
    {
        int j = t >> 5, u = t & 31;
        pqb[j][u] = pb[(q0 + j)*NU + u] + bh[u];
    }
    __syncthreads();

    float e[8];
    #pragma unroll
    for (int j = 0; j < 8; j++){
        float acc = 0.f;
        #pragma unroll
        for (int u = 0; u < 32; u++)
            acc = fmaf(was[u], tanh_approx(pqb[j][u] + ps[t][u]), acc);
        float alpha = acc + ba0;
        float sg = 1.f / (1.f + __expf(-alpha));
        e[j] = __expf(sg);
    }

    #pragma unroll
    for (int j = 0; j < 8; j++){
        float w = e[j];
        #pragma unroll
        for (int o = 16; o > 0; o >>= 1) w += __shfl_xor_sync(0xffffffffu, w, o);
        if ((t & 31) == 0) red[t >> 5][j] = w;
    }
    __syncthreads();
    if (t < 8){
        float tot = 0.f;
        #pragma unroll
        for (int w = 0; w < 8; w++) tot += red[w][t];
        inv[t] = 1.f / tot;
    }
    __syncthreads();

    #pragma unroll
    for (int j = 0; j < 8; j++)
        g_af[(size_t)b*NL*NL + (size_t)(q0 + j)*NL + t] = __float2half(e[j] * inv[j]);
}

// ---------------------------------------------------------------------------
// K_out: out[b,q,f] = sum_k a[b,q,k]*x[b,k,f]
// fp16-ACC HMMA in k=32 groups, promoted to fp32 registers per group.
// BM=128, BN=128, BK=64 (4 chunks); 8 warps 2(M)x4(N), warp tile 64x32.
// 3-stage cp.async.cg ring, one wait_group(1)+barrier per chunk.
// grid (49, 2, 8), 256 threads, 2 CTA/SM.
// ---------------------------------------------------------------------------
// stage layout (bytes): Af 128*72*2 = 18432 | Bf 64*136*2 = 17408 -> 35840
#define STG    35840
#define OFF_B  18432
#define K3_SMEM (3*STG)

__global__ __launch_bounds__(256, 2) void k_out(float* __restrict__ out){
    extern __shared__ char sm[];
    const uint32_t smb = s2u(sm);
    const int t = threadIdx.x, wid = t >> 5, l = t & 31;
    const int lr = l & 15, lc = (l >> 4) << 3;
    const int b  = blockIdx.z;
    const int q0 = blockIdx.y * 128;
    const int f0 = blockIdx.x * 128;
    const int warp_m = wid >> 2, warp_n = wid & 3;   // 2 x 4

    const __half* gaf = g_af + ((size_t)b*NL + q0)*NL;
    const __half* gx  = g_xh + (size_t)b*NL*NF + f0;

    // A staging: 128 rows x 64 halves = 1024 x 16B -> 4 cp16/thread
    int aR[4];
    #pragma unroll
    for (int i = 0; i < 4; i++) aR[i] = (t + i*256) >> 3;   // 0..127
    const int aC = (t & 7)*8;                               // halves
    // B staging: 64 rows x 128 halves = 1024 x 16B -> 4 cp16/thread
    int bR[4];
    #pragma unroll
    for (int i = 0; i < 4; i++) bR[i] = (t + i*256) >> 4;   // 0..63
    const int bC = (t & 15)*8;                              // halves

    float acc[4][4][4];
    #pragma unroll
    for (int mt = 0; mt < 4; mt++)
        #pragma unroll
        for (int ng = 0; ng < 4; ng++)
            #pragma unroll
            for (int k = 0; k < 4; k++) acc[mt][ng][k] = 0.f;

    // ---- prologue: issue chunks 0 and 1 into stages 0,1 (separate groups)
    #pragma unroll
    for (int c = 0; c < 2; c++){
        const uint32_t st = smb + c*STG;
        const int k0 = c*64;
        #pragma unroll
        for (int i = 0; i < 4; i++){
            cp16(st + (uint32_t)aR[i]*144 + aC*2,          gaf + (size_t)aR[i]*NL + k0 + aC);
            cp16(st + OFF_B + (uint32_t)bR[i]*272 + bC*2,  gx + (size_t)(k0 + bR[i])*NF + bC);
        }
        cp_commit();
    }

    for (int c = 0; c < 4; c++){
        cp_wait1();            // chunk c's group complete (c+1 may remain in flight)
        __syncthreads();       // visible; all warps done with stage (c+2)%3

        if (c < 2){            // issue chunk c+2
            const uint32_t st = smb + ((c+2)%3)*STG;
            const int k0 = (c+2)*64;
            #pragma unroll
            for (int i = 0; i < 4; i++){
                cp16(st + (uint32_t)aR[i]*144 + aC*2,         gaf + (size_t)aR[i]*NL + k0 + aC);
                cp16(st + OFF_B + (uint32_t)bR[i]*272 + bC*2, gx + (size_t)(k0 + bR[i])*NF + bC);
            }
        }
        cp_commit();

        const uint32_t base = smb + (c % 3)*STG;
        #pragma unroll
        for (int kp = 0; kp < 2; kp++){        // k=32 groups within the chunk
            const int ks0 = kp*32, ks1 = kp*32 + 16;
            uint32_t fb4[2][8];
            ldsm4t(fb4[0] + 0, base + OFF_B + ((ks0 + lr)*136 + warp_n*32 + 0  + lc)*2);
            ldsm4t(fb4[0] + 4, base + OFF_B + ((ks0 + lr)*136 + warp_n*32 + 16 + lc)*2);
            ldsm4t(fb4[1] + 0, base + OFF_B + ((ks1 + lr)*136 + warp_n*32 + 0  + lc)*2);
            ldsm4t(fb4[1] + 4, base + OFF_B + ((ks1 + lr)*136 + warp_n*32 + 16 + lc)*2);
            #pragma unroll
            for (int mt = 0; mt < 4; mt++){
                uint32_t fa0[4], fa1[4];
                ldsm4(fa0, base + ((warp_m*64 + mt*16 + lr)*72 + ks0 + lc)*2);
                ldsm4(fa1, base + ((warp_m*64 + mt*16 + lr)*72 + ks1 + lc)*2);
                #pragma unroll
                for (int ng = 0; ng < 4; ng++){
                    uint32_t d[2] = {0u, 0u};
                    mma_f16acc(d, fa0, fb4[0][ng*2], fb4[0][ng*2+1]);
                    mma_f16acc(d, fa1, fb4[1][ng*2], fb4[1][ng*2+1]);
                    float2 f0 = __half22float2(*(__half2*)&d[0]);
                    float2 f1 = __half22float2(*(__half2*)&d[1]);
                    acc[mt][ng][0] += f0.x;
                    acc[mt][ng][1] += f0.y;
                    acc[mt][ng][2] += f1.x;
                    acc[mt][ng][3] += f1.y;
                }
            }
        }
    }

    // epilogue
    const int c0 = (l & 3)*2;
    #pragma unroll
    for (int mt = 0; mt < 4; mt++){
        const int row = q0 + warp_m*64 + mt*16 + (l >> 2);
        #pragma unroll
        for (int ng = 0; ng < 4; ng++){
            const int col = f0 + warp_n*32 + ng*8 + c0;
            *(float2*)&out[((size_t)(b*NL + row))*NF + col] =
                make_float2(acc[mt][ng][0], acc[mt][ng][1]);
            *(float2*)&out[((size_t)(b*NL + row + 8))*NF + col] =
                make_float2(acc[mt][ng][2], acc[mt][ng][3]);
        }
    }
}

// ---------------------------------------------------------------------------
extern "C" void kernel_launch(void* const* d_in, const int* in_sizes, int n_in,
                              void* d_out, int out_size){
    const float* inp = (const float*)d_in[0];
    const float* Wt  = (const float*)d_in[1];
    const float* bh  = (const float*)d_in[2];
    const float* Wa  = (const float*)d_in[3];
    const float* ba  = (const float*)d_in[4];
    float* out = (float*)d_out;

    static bool attr_set = false;
    if (!attr_set){
        cudaFuncSetAttribute(k_out, cudaFuncAttributeMaxDynamicSharedMemorySize, K3_SMEM);
        attr_set = true;
    }

    void* gp_addr = nullptr;
    cudaGetSymbolAddress(&gp_addr, g_p);
    cudaMemsetAsync(gp_addr, 0, sizeof(float)*NB*NL*NU);

    k_proj<<<dim3(16, KSPLIT), 256>>>(inp, Wt);
    k_attn<<<dim3(NL/8, NB), 256>>>(bh, Wa, ba);
    k_out<<<dim3(NF/128, NL/128, NB), 256, K3_SMEM>>>(out);
}

// round 13
// speedup vs baseline: 1.1094x; 1.1094x over previous
#include <cuda_runtime.h>
#include <cuda_fp16.h>
#include <cstdint>

#define NB 8
#define NL 256
#define NF 6272
#define NU 32
#define KSPLIT 28

// Scratch (no cudaMalloc allowed)
__device__ float g_p[NB*NL*NU];                      // projections (atomic-accumulated)
__device__ __half g_af[NB*NL*NL];                    // a (softmax) fp16 [b][q][k]
__device__ __half g_xh[(size_t)NB*NL*NF];            // inputs fp16 [b][k][f] (written by k_proj)

// ---------------------------------------------------------------------------
// helpers
// ---------------------------------------------------------------------------
__device__ __forceinline__ uint32_t s2u(const void* p){
    uint32_t a;
    asm("{ .reg .u64 t; cvta.to.shared.u64 t, %1; cvt.u32.u64 %0, t; }" : "=r"(a) : "l"(p));
    return a;
}
__device__ __forceinline__ float tanh_approx(float x){
    float y; asm("tanh.approx.f32 %0, %1;" : "=f"(y) : "f"(x)); return y;
}
__device__ __forceinline__ void ldsm4(uint32_t r[4], uint32_t a){
    asm volatile("ldmatrix.sync.aligned.m8n8.x4.shared.b16 {%0,%1,%2,%3}, [%4];"
                 : "=r"(r[0]), "=r"(r[1]), "=r"(r[2]), "=r"(r[3]) : "r"(a));
}
__device__ __forceinline__ void ldsm4t(uint32_t r[4], uint32_t a){
    asm volatile("ldmatrix.sync.aligned.m8n8.x4.trans.shared.b16 {%0,%1,%2,%3}, [%4];"
                 : "=r"(r[0]), "=r"(r[1]), "=r"(r[2]), "=r"(r[3]) : "r"(a));
}
__device__ __forceinline__ void mma_f16(float c[4], const uint32_t a[4], uint32_t b0, uint32_t b1){
    asm volatile(
        "mma.sync.aligned.m16n8k16.row.col.f32.f16.f16.f32 "
        "{%0,%1,%2,%3}, {%4,%5,%6,%7}, {%8,%9}, {%0,%1,%2,%3};"
        : "+f"(c[0]), "+f"(c[1]), "+f"(c[2]), "+f"(c[3])
        : "r"(a[0]), "r"(a[1]), "r"(a[2]), "r"(a[3]), "r"(b0), "r"(b1));
}
__device__ __forceinline__ uint2 cvt4h(float4 v){
    __half h[4];
    h[0] = __float2half(v.x); h[1] = __float2half(v.y);
    h[2] = __float2half(v.z); h[3] = __float2half(v.w);
    return *(uint2*)h;
}
__device__ __forceinline__ void cp16(uint32_t dst, const void* src){
    asm volatile("cp.async.cg.shared.global [%0], [%1], 16;" :: "r"(dst), "l"(src));
}
__device__ __forceinline__ void cp_commit(){ asm volatile("cp.async.commit_group;"); }
__device__ __forceinline__ void cp_wait1(){ asm volatile("cp.async.wait_group 1;"); }

// ---------------------------------------------------------------------------
// K_proj: g_p += x[rows, fchunk] @ Wt[fchunk, 32]  (fp16 HMMA, atomic partials)
// Double-buffered smem: ONE barrier per iteration; staging of iter s+1
// overlaps MMA of iter s. Also writes g_xh (inputs as fp16).
// grid (16, 28), 256 threads, f-chunk 224.
// ---------------------------------------------------------------------------
__global__ __launch_bounds__(256) void k_proj(const float* __restrict__ inp,
                                              const float* __restrict__ Wt){
    __shared__ __half Ah[2][128][40];
    __shared__ __half Bh[2][32][40];
    const int t = threadIdx.x, wid = t >> 5, l = t & 31;
    const int lr = l & 15, lc = (l >> 4) << 3;
    const int row0 = blockIdx.x * 128;
    const int fb0  = blockIdx.y * 224;

    const int arR[4] = { (t+0)>>3, (t+256)>>3, (t+512)>>3, (t+768)>>3 };
    const int arC    = (t & 7)*4;
    const int wrR    = t >> 3, wrC = (t & 7)*4;

    float acc[4][4];
    #pragma unroll
    for (int i = 0; i < 4; i++)
        #pragma unroll
        for (int j = 0; j < 4; j++) acc[i][j] = 0.f;

    const uint32_t a_ah = s2u(Ah), a_bh = s2u(Bh);

    float4 xv[4], wv;
    #pragma unroll
    for (int i = 0; i < 4; i++)
        xv[i] = *(const float4*)(inp + (size_t)(row0 + arR[i])*NF + fb0 + arC);
    wv = *(const float4*)(Wt + (size_t)(fb0 + wrR)*NU + wrC);

    for (int s = 0; s < 7; s++){
        const int fb = fb0 + s*32;
        const int cur = s & 1;
        // store current regs -> smem buffer cur (+ write-through g_xh)
        #pragma unroll
        for (int i = 0; i < 4; i++){
            uint2 h = cvt4h(xv[i]);
            *(uint2*)&Ah[cur][arR[i]][arC] = h;
            *(uint2*)&g_xh[(size_t)(row0 + arR[i])*NF + fb + arC] = h;
        }
        *(uint2*)&Bh[cur][wrR][wrC] = cvt4h(wv);

        // prefetch next chunk into regs (overlaps sync + MMA below)
        if (s < 6){
            const int fbn = fb0 + (s+1)*32;
            #pragma unroll
            for (int i = 0; i < 4; i++)
                xv[i] = *(const float4*)(inp + (size_t)(row0 + arR[i])*NF + fbn + arC);
            wv = *(const float4*)(Wt + (size_t)(fbn + wrR)*NU + wrC);
        }
        __syncthreads();   // buffer cur fully staged; buffer cur^1 free (MMA of s-1 done pre-barrier)

        const uint32_t ab = a_ah + cur*10240;   // 128*40*2
        const uint32_t bb = a_bh + cur*2560;    // 32*40*2
        #pragma unroll
        for (int ks = 0; ks < 32; ks += 16){
            uint32_t fa[4];
            ldsm4(fa, ab + ((wid*16 + lr)*40 + ks + lc)*2);
            uint32_t fb4[8];
            ldsm4t(fb4 + 0, bb + ((ks + lr)*40 + 0  + lc)*2);
            ldsm4t(fb4 + 4, bb + ((ks + lr)*40 + 16 + lc)*2);
            #pragma unroll
            for (int ng = 0; ng < 4; ng++)
                mma_f16(acc[ng], fa, fb4[ng*2], fb4[ng*2+1]);
        }
        // no second barrier: next iter stores to the OTHER buffer; reuse of this
        // buffer happens only after the NEXT barrier.
    }
    const int r0 = row0 + wid*16 + (l >> 2);
    const int c0 = (l & 3)*2;
    #pragma unroll
    for (int ng = 0; ng < 4; ng++){
        atomicAdd(&g_p[(size_t)r0*NU + ng*8 + c0],     acc[ng][0]);
        atomicAdd(&g_p[(size_t)r0*NU + ng*8 + c0 + 1], acc[ng][1]);
        atomicAdd(&g_p[(size_t)(r0+8)*NU + ng*8 + c0],     acc[ng][2]);
        atomicAdd(&g_p[(size_t)(r0+8)*NU + ng*8 + c0 + 1], acc[ng][3]);
    }
}

// ---------------------------------------------------------------------------
// K_attn: block handles (b, 16 queries). grid (16, 8) = 128 blocks (1 wave).
// 256 threads (t = k).
// ---------------------------------------------------------------------------
__global__ __launch_bounds__(256) void k_attn(const float* __restrict__ bh,
                                              const float* __restrict__ Wa,
                                              const float* __restrict__ ba){
    __shared__ float ps[NL][33];
    __shared__ float pqb[16][32];
    __shared__ float was[32];
    __shared__ float red[8][16];
    __shared__ float inv[16];

    const int t = threadIdx.x;
    const int b = blockIdx.y;
    const int q0 = blockIdx.x * 16;
    const float* pb = g_p + b*NL*NU;
    const float ba0 = ba[0];

    #pragma unroll
    for (int i = 0; i < 32; i++){
        int idx = t + i*256;
        ps[idx >> 5][idx & 31] = pb[idx];
    }
    if (t < 32) was[t] = Wa[t];
    #pragma unroll
    for (int i = 0; i < 2; i++){
        int e = t + i*256;               // 512 entries = 16 q x 32 u
        int j = e >> 5, u = e & 31;
        pqb[j][u] = pb[(q0 + j)*NU + u] + bh[u];
    }
    __syncthreads();

    float e[16];
    #pragma unroll
    for (int j = 0; j < 16; j++){
        float acc = 0.f;
        #pragma unroll
        for (int u = 0; u < 32; u++)
            acc = fmaf(was[u], tanh_approx(pqb[j][u] + ps[t][u]), acc);
        float alpha = acc + ba0;
        float sg = 1.f / (1.f + __expf(-alpha));
        e[j] = __expf(sg);
    }

    #pragma unroll
    for (int j = 0; j < 16; j++){
        float w = e[j];
        #pragma unroll
        for (int o = 16; o > 0; o >>= 1) w += __shfl_xor_sync(0xffffffffu, w, o);
        if ((t & 31) == 0) red[t >> 5][j] = w;
    }
    __syncthreads();
    if (t < 16){
        float tot = 0.f;
        #pragma unroll
        for (int w = 0; w < 8; w++) tot += red[w][t];
        inv[t] = 1.f / tot;
    }
    __syncthreads();

    #pragma unroll
    for (int j = 0; j < 16; j++)
        g_af[(size_t)b*NL*NL + (size_t)(q0 + j)*NL + t] = __float2half(e[j] * inv[j]);
}

// ---------------------------------------------------------------------------
// K_out: out[b,q,f] = sum_k a[b,q,k]*x[b,k,f]   (single fp16 HMMA term)
// IDENTICAL to R10 (best measured): BM=128, BN=128, BK=64; 8 warps 2x4,
// warp tile 64x32; 3-stage cp.async.cg ring, one wait_group(1)+barrier/chunk.
// grid (49, 2, 8), 256 threads, 2 CTA/SM.
// ---------------------------------------------------------------------------
// stage layout (bytes): Af 128*72*2 = 18432 | Bf 64*136*2 = 17408 -> 35840
#define STG    35840
#define OFF_B  18432
#define K3_SMEM (3*STG)

__global__ __launch_bounds__(256, 2) void k_out(float* __restrict__ out){
    extern __shared__ char sm[];
    const uint32_t smb = s2u(sm);
    const int t = threadIdx.x, wid = t >> 5, l = t & 31;
    const int lr = l & 15, lc = (l >> 4) << 3;
    const int b  = blockIdx.z;
    const int q0 = blockIdx.y * 128;
    const int f0 = blockIdx.x * 128;
    const int warp_m = wid >> 2, warp_n = wid & 3;   // 2 x 4

    const __half* gaf = g_af + ((size_t)b*NL + q0)*NL;
    const __half* gx  = g_xh + (size_t)b*NL*NF + f0;

    int aR[4];
    #pragma unroll
    for (int i = 0; i < 4; i++) aR[i] = (t + i*256) >> 3;   // 0..127
    const int aC = (t & 7)*8;
    int bR[4];
    #pragma unroll
    for (int i = 0; i < 4; i++) bR[i] = (t + i*256) >> 4;   // 0..63
    const int bC = (t & 15)*8;

    float acc[4][4][4];
    #pragma unroll
    for (int mt = 0; mt < 4; mt++)
        #pragma unroll
        for (int ng = 0; ng < 4; ng++)
            #pragma unroll
            for (int k = 0; k < 4; k++) acc[mt][ng][k] = 0.f;

    #pragma unroll
    for (int c = 0; c < 2; c++){
        const uint32_t st = smb + c*STG;
        const int k0 = c*64;
        #pragma unroll
        for (int i = 0; i < 4; i++){
            cp16(st + (uint32_t)aR[i]*144 + aC*2,          gaf + (size_t)aR[i]*NL + k0 + aC);
            cp16(st + OFF_B + (uint32_t)bR[i]*272 + bC*2,  gx + (size_t)(k0 + bR[i])*NF + bC);
        }
        cp_commit();
    }

    for (int c = 0; c < 4; c++){
        cp_wait1();
        __syncthreads();

        if (c < 2){
            const uint32_t st = smb + ((c+2)%3)*STG;
            const int k0 = (c+2)*64;
            #pragma unroll
            for (int i = 0; i < 4; i++){
                cp16(st + (uint32_t)aR[i]*144 + aC*2,         gaf + (size_t)aR[i]*NL + k0 + aC);
                cp16(st + OFF_B + (uint32_t)bR[i]*272 + bC*2, gx + (size_t)(k0 + bR[i])*NF + bC);
            }
        }
        cp_commit();

        const uint32_t base = smb + (c % 3)*STG;
        #pragma unroll
        for (int ks = 0; ks < 64; ks += 16){
            uint32_t fb4[8];
            ldsm4t(fb4 + 0, base + OFF_B + ((ks + lr)*136 + warp_n*32 + 0  + lc)*2);
            ldsm4t(fb4 + 4, base + OFF_B + ((ks + lr)*136 + warp_n*32 + 16 + lc)*2);
            #pragma unroll
            for (int mt = 0; mt < 4; mt++){
                uint32_t fa[4];
                ldsm4(fa, base + ((warp_m*64 + mt*16 + lr)*72 + ks + lc)*2);
                #pragma unroll
                for (int ng = 0; ng < 4; ng++)
                    mma_f16(acc[mt][ng], fa, fb4[ng*2], fb4[ng*2+1]);
            }
        }
    }

    const int c0 = (l & 3)*2;
    #pragma unroll
    for (int mt = 0; mt < 4; mt++){
        const int row = q0 + warp_m*64 + mt*16 + (l >> 2);
        #pragma unroll
        for (int ng = 0; ng < 4; ng++){
            const int col = f0 + warp_n*32 + ng*8 + c0;
            *(float2*)&out[((size_t)(b*NL + row))*NF + col] =
                make_float2(acc[mt][ng][0], acc[mt][ng][1]);
            *(float2*)&out[((size_t)(b*NL + row + 8))*NF + col] =
                make_float2(acc[mt][ng][2], acc[mt][ng][3]);
        }
    }
}

// ---------------------------------------------------------------------------
extern "C" void kernel_launch(void* const* d_in, const int* in_sizes, int n_in,
                              void* d_out, int out_size){
    const float* inp = (const float*)d_in[0];
    const float* Wt  = (const float*)d_in[1];
    const float* bh  = (const float*)d_in[2];
    const float* Wa  = (const float*)d_in[3];
    const float* ba  = (const float*)d_in[4];
    float* out = (float*)d_out;

    static bool attr_set = false;
    if (!attr_set){
        cudaFuncSetAttribute(k_out, cudaFuncAttributeMaxDynamicSharedMemorySize, K3_SMEM);
        attr_set = true;
    }

    void* gp_addr = nullptr;
    cudaGetSymbolAddress(&gp_addr, g_p);
    cudaMemsetAsync(gp_addr, 0, sizeof(float)*NB*NL*NU);

    k_proj<<<dim3(16, KSPLIT), 256>>>(inp, Wt);
    k_attn<<<dim3(NL/16, NB), 256>>>(bh, Wa, ba);
    k_out<<<dim3(NF/128, NL/128, NB), 256, K3_SMEM>>>(out);
}

// round 14
// speedup vs baseline: 1.1376x; 1.0254x over previous
#include <cuda_runtime.h>
#include <cuda_fp16.h>
#include <cstdint>

#define NB 8
#define NL 256
#define NF 6272
#define NU 32
#define KSPLIT 28

// Scratch (no cudaMalloc allowed)
__device__ float g_p[NB*NL*NU];                      // projections (atomic-accumulated)
__device__ __half g_af[NB*NL*NL];                    // a (softmax) fp16 [b][q][k]
__device__ __half g_xh[(size_t)NB*NL*NF];            // inputs fp16 [b][k][f] (written by k_proj)

// ---------------------------------------------------------------------------
// helpers
// ---------------------------------------------------------------------------
__device__ __forceinline__ uint32_t s2u(const void* p){
    uint32_t a;
    asm("{ .reg .u64 t; cvta.to.shared.u64 t, %1; cvt.u32.u64 %0, t; }" : "=r"(a) : "l"(p));
    return a;
}
__device__ __forceinline__ float tanh_approx(float x){
    float y; asm("tanh.approx.f32 %0, %1;" : "=f"(y) : "f"(x)); return y;
}
__device__ __forceinline__ void ldsm4(uint32_t r[4], uint32_t a){
    asm volatile("ldmatrix.sync.aligned.m8n8.x4.shared.b16 {%0,%1,%2,%3}, [%4];"
                 : "=r"(r[0]), "=r"(r[1]), "=r"(r[2]), "=r"(r[3]) : "r"(a));
}
__device__ __forceinline__ void ldsm4t(uint32_t r[4], uint32_t a){
    asm volatile("ldmatrix.sync.aligned.m8n8.x4.trans.shared.b16 {%0,%1,%2,%3}, [%4];"
                 : "=r"(r[0]), "=r"(r[1]), "=r"(r[2]), "=r"(r[3]) : "r"(a));
}
__device__ __forceinline__ void mma_f16(float c[4], const uint32_t a[4], uint32_t b0, uint32_t b1){
    asm volatile(
        "mma.sync.aligned.m16n8k16.row.col.f32.f16.f16.f32 "
        "{%0,%1,%2,%3}, {%4,%5,%6,%7}, {%8,%9}, {%0,%1,%2,%3};"
        : "+f"(c[0]), "+f"(c[1]), "+f"(c[2]), "+f"(c[3])
        : "r"(a[0]), "r"(a[1]), "r"(a[2]), "r"(a[3]), "r"(b0), "r"(b1));
}
__device__ __forceinline__ uint2 cvt4h(float4 v){
    __half h[4];
    h[0] = __float2half(v.x); h[1] = __float2half(v.y);
    h[2] = __float2half(v.z); h[3] = __float2half(v.w);
    return *(uint2*)h;
}
__device__ __forceinline__ void cp16(uint32_t dst, const void* src){
    asm volatile("cp.async.cg.shared.global [%0], [%1], 16;" :: "r"(dst), "l"(src));
}
__device__ __forceinline__ void cp_commit(){ asm volatile("cp.async.commit_group;"); }
__device__ __forceinline__ void cp_wait1(){ asm volatile("cp.async.wait_group 1;"); }

// ---------------------------------------------------------------------------
// K_proj: g_p += x[rows, fchunk] @ Wt[fchunk, 32]  (fp16 HMMA, atomic partials)
// cp.async fp32 3-stage ring (2 chunks in flight); each thread converts
// EXACTLY the bytes its own cp wrote (no barrier needed copy->convert).
// Writes g_xh (inputs fp16) as byproduct. grid (16, 28), 256 thr, 3 CTA/SM.
// ---------------------------------------------------------------------------
// dynamic smem layout (bytes):
//   Xf: 3 stages x 128 rows x 32 fp32 = 3*16384 = 49152
//   Wf: 3 stages x  32 rows x 32 fp32 = 3*4096  = 12288
//   Ah: 128 x 40 fp16 = 10240
//   Bh:  32 x 40 fp16 = 2560
#define P_OFF_WF 49152
#define P_OFF_AH 61440
#define P_OFF_BH 71680
#define P_SMEM   74240

__global__ __launch_bounds__(256) void k_proj(const float* __restrict__ inp,
                                              const float* __restrict__ Wt){
    extern __shared__ char sm[];
    const uint32_t smb = s2u(sm);
    const int t = threadIdx.x, wid = t >> 5, l = t & 31;
    const int lr = l & 15, lc = (l >> 4) << 3;
    const int row0 = blockIdx.x * 128;
    const int fb0  = blockIdx.y * 224;

    // per-thread tile coords: 4 rows x one 4-float chunk
    const int r0t = t >> 3;                 // 0..31 (+32*i)
    const int colf = (t & 7)*4;             // float offset within row

    float acc[4][4];
    #pragma unroll
    for (int i = 0; i < 4; i++)
        #pragma unroll
        for (int j = 0; j < 4; j++) acc[i][j] = 0.f;

    const uint32_t a_ah = smb + P_OFF_AH, a_bh = smb + P_OFF_BH;

    // ---- prologue: issue stages 0,1
    #pragma unroll
    for (int s = 0; s < 2; s++){
        const int fb = fb0 + s*32;
        const uint32_t xst = smb + s*16384;
        const uint32_t wst = smb + P_OFF_WF + s*4096;
        #pragma unroll
        for (int i = 0; i < 4; i++){
            int r = r0t + 32*i;
            cp16(xst + (uint32_t)r*128 + colf*4, inp + (size_t)(row0 + r)*NF + fb + colf);
        }
        cp16(wst + (uint32_t)r0t*128 + colf*4, Wt + (size_t)(fb + r0t)*NU + colf);
        cp_commit();
    }

    for (int s = 0; s < 7; s++){
        cp_wait1();                          // stage s complete (s+1 may be in flight)
        const int fb = fb0 + s*32;
        const uint32_t xst = smb + (s % 3)*16384;
        const uint32_t wst = smb + P_OFF_WF + (s % 3)*4096;

        // convert own bytes: fp32 smem -> fp16 smem (+ write-through g_xh)
        #pragma unroll
        for (int i = 0; i < 4; i++){
            int r = r0t + 32*i;
            float4 v = *(const float4*)(sm + (xst - smb) + (uint32_t)r*128 + colf*4);
            uint2 h = cvt4h(v);
            *(uint2*)(sm + P_OFF_AH + (uint32_t)r*80 + colf*2) = h;
            *(uint2*)&g_xh[(size_t)(row0 + r)*NF + fb + colf] = h;
        }
        {
            float4 v = *(const float4*)(sm + P_OFF_WF + (s%3)*4096 + (uint32_t)r0t*128 + colf*4);
            *(uint2*)(sm + P_OFF_BH + (uint32_t)r0t*80 + colf*2) = cvt4h(v);
        }

        // issue stage s+2 into freed ring slot ((s+2)%3 held stage s-1; this
        // thread finished converting it last iteration, and only this thread
        // ever touches these bytes)
        if (s < 5){
            const int fbn = fb0 + (s+2)*32;
            const uint32_t xs2 = smb + ((s+2) % 3)*16384;
            const uint32_t ws2 = smb + P_OFF_WF + ((s+2) % 3)*4096;
            #pragma unroll
            for (int i = 0; i < 4; i++){
                int r = r0t + 32*i;
                cp16(xs2 + (uint32_t)r*128 + colf*4, inp + (size_t)(row0 + r)*NF + fbn + colf);
            }
            cp16(ws2 + (uint32_t)r0t*128 + colf*4, Wt + (size_t)(fbn + r0t)*NU + colf);
        }
        cp_commit();                         // uniform group accounting

        __syncthreads();                     // Ah/Bh staged by all threads

        #pragma unroll
        for (int ks = 0; ks < 32; ks += 16){
            uint32_t fa[4];
            ldsm4(fa, a_ah + ((wid*16 + lr)*40 + ks + lc)*2);
            uint32_t fb4[8];
            ldsm4t(fb4 + 0, a_bh + ((ks + lr)*40 + 0  + lc)*2);
            ldsm4t(fb4 + 4, a_bh + ((ks + lr)*40 + 16 + lc)*2);
            #pragma unroll
            for (int ng = 0; ng < 4; ng++)
                mma_f16(acc[ng], fa, fb4[ng*2], fb4[ng*2+1]);
        }
        __syncthreads();                     // Ah/Bh consumed; safe to overwrite
    }

    const int r0 = row0 + wid*16 + (l >> 2);
    const int c0 = (l & 3)*2;
    #pragma unroll
    for (int ng = 0; ng < 4; ng++){
        atomicAdd(&g_p[(size_t)r0*NU + ng*8 + c0],     acc[ng][0]);
        atomicAdd(&g_p[(size_t)r0*NU + ng*8 + c0 + 1], acc[ng][1]);
        atomicAdd(&g_p[(size_t)(r0+8)*NU + ng*8 + c0],     acc[ng][2]);
        atomicAdd(&g_p[(size_t)(r0+8)*NU + ng*8 + c0 + 1], acc[ng][3]);
    }
}

// ---------------------------------------------------------------------------
// K_attn: block handles (b, 16 queries). grid (16, 8) = 128 blocks (1 wave).
// ---------------------------------------------------------------------------
__global__ __launch_bounds__(256) void k_attn(const float* __restrict__ bh,
                                              const float* __restrict__ Wa,
                                              const float* __restrict__ ba){
    __shared__ float ps[NL][33];
    __shared__ float pqb[16][32];
    __shared__ float was[32];
    __shared__ float red[8][16];
    __shared__ float inv[16];

    const int t = threadIdx.x;
    const int b = blockIdx.y;
    const int q0 = blockIdx.x * 16;
    const float* pb = g_p + b*NL*NU;
    const float ba0 = ba[0];

    #pragma unroll
    for (int i = 0; i < 32; i++){
        int idx = t + i*256;
        ps[idx >> 5][idx & 31] = pb[idx];
    }
    if (t < 32) was[t] = Wa[t];
    #pragma unroll
    for (int i = 0; i < 2; i++){
        int e = t + i*256;
        int j = e >> 5, u = e & 31;
        pqb[j][u] = pb[(q0 + j)*NU + u] + bh[u];
    }
    __syncthreads();

    float e[16];
    #pragma unroll
    for (int j = 0; j < 16; j++){
        float acc = 0.f;
        #pragma unroll
        for (int u = 0; u < 32; u++)
            acc = fmaf(was[u], tanh_approx(pqb[j][u] + ps[t][u]), acc);
        float alpha = acc + ba0;
        float sg = 1.f / (1.f + __expf(-alpha));
        e[j] = __expf(sg);
    }

    #pragma unroll
    for (int j = 0; j < 16; j++){
        float w = e[j];
        #pragma unroll
        for (int o = 16; o > 0; o >>= 1) w += __shfl_xor_sync(0xffffffffu, w, o);
        if ((t & 31) == 0) red[t >> 5][j] = w;
    }
    __syncthreads();
    if (t < 16){
        float tot = 0.f;
        #pragma unroll
        for (int w = 0; w < 8; w++) tot += red[w][t];
        inv[t] = 1.f / tot;
    }
    __syncthreads();

    #pragma unroll
    for (int j = 0; j < 16; j++)
        g_af[(size_t)b*NL*NL + (size_t)(q0 + j)*NL + t] = __float2half(e[j] * inv[j]);
}

// ---------------------------------------------------------------------------
// K_out: IDENTICAL to R10/R13 best: BM=128, BN=128, BK=64; 8 warps 2x4,
// warp tile 64x32; 3-stage cp.async.cg ring, one wait_group(1)+barrier/chunk.
// grid (49, 2, 8), 256 threads, 2 CTA/SM.
// ---------------------------------------------------------------------------
#define STG    35840
#define OFF_B  18432
#define K3_SMEM (3*STG)

__global__ __launch_bounds__(256, 2) void k_out(float* __restrict__ out){
    extern __shared__ char sm[];
    const uint32_t smb = s2u(sm);
    const int t = threadIdx.x, wid = t >> 5, l = t & 31;
    const int lr = l & 15, lc = (l >> 4) << 3;
    const int b  = blockIdx.z;
    const int q0 = blockIdx.y * 128;
    const int f0 = blockIdx.x * 128;
    const int warp_m = wid >> 2, warp_n = wid & 3;

    const __half* gaf = g_af + ((size_t)b*NL + q0)*NL;
    const __half* gx  = g_xh + (size_t)b*NL*NF + f0;

    int aR[4];
    #pragma unroll
    for (int i = 0; i < 4; i++) aR[i] = (t + i*256) >> 3;
    const int aC = (t & 7)*8;
    int bR[4];
    #pragma unroll
    for (int i = 0; i < 4; i++) bR[i] = (t + i*256) >> 4;
    const int bC = (t & 15)*8;

    float acc[4][4][4];
    #pragma unroll
    for (int mt = 0; mt < 4; mt++)
        #pragma unroll
        for (int ng = 0; ng < 4; ng++)
            #pragma unroll
            for (int k = 0; k < 4; k++) acc[mt][ng][k] = 0.f;

    #pragma unroll
    for (int c = 0; c < 2; c++){
        const uint32_t st = smb + c*STG;
        const int k0 = c*64;
        #pragma unroll
        for (int i = 0; i < 4; i++){
            cp16(st + (uint32_t)aR[i]*144 + aC*2,          gaf + (size_t)aR[i]*NL + k0 + aC);
            cp16(st + OFF_B + (uint32_t)bR[i]*272 + bC*2,  gx + (size_t)(k0 + bR[i])*NF + bC);
        }
        cp_commit();
    }

    for (int c = 0; c < 4; c++){
        cp_wait1();
        __syncthreads();

        if (c < 2){
            const uint32_t st = smb + ((c+2)%3)*STG;
            const int k0 = (c+2)*64;
            #pragma unroll
            for (int i = 0; i < 4; i++){
                cp16(st + (uint32_t)aR[i]*144 + aC*2,         gaf + (size_t)aR[i]*NL + k0 + aC);
                cp16(st + OFF_B + (uint32_t)bR[i]*272 + bC*2, gx + (size_t)(k0 + bR[i])*NF + bC);
            }
        }
        cp_commit();

        const uint32_t base = smb + (c % 3)*STG;
        #pragma unroll
        for (int ks = 0; ks < 64; ks += 16){
            uint32_t fb4[8];
            ldsm4t(fb4 + 0, base + OFF_B + ((ks + lr)*136 + warp_n*32 + 0  + lc)*2);
            ldsm4t(fb4 + 4, base + OFF_B + ((ks + lr)*136 + warp_n*32 + 16 + lc)*2);
            #pragma unroll
            for (int mt = 0; mt < 4; mt++){
                uint32_t fa[4];
                ldsm4(fa, base + ((warp_m*64 + mt*16 + lr)*72 + ks + lc)*2);
                #pragma unroll
                for (int ng = 0; ng < 4; ng++)
                    mma_f16(acc[mt][ng], fa, fb4[ng*2], fb4[ng*2+1]);
            }
        }
    }

    const int c0 = (l & 3)*2;
    #pragma unroll
    for (int mt = 0; mt < 4; mt++){
        const int row = q0 + warp_m*64 + mt*16 + (l >> 2);
        #pragma unroll
        for (int ng = 0; ng < 4; ng++){
            const int col = f0 + warp_n*32 + ng*8 + c0;
            *(float2*)&out[((size_t)(b*NL + row))*NF + col] =
                make_float2(acc[mt][ng][0], acc[mt][ng][1]);
            *(float2*)&out[((size_t)(b*NL + row + 8))*NF + col] =
                make_float2(acc[mt][ng][2], acc[mt][ng][3]);
        }
    }
}

// ---------------------------------------------------------------------------
extern "C" void kernel_launch(void* const* d_in, const int* in_sizes, int n_in,
                              void* d_out, int out_size){
    const float* inp = (const float*)d_in[0];
    const float* Wt  = (const float*)d_in[1];
    const float* bh  = (const float*)d_in[2];
    const float* Wa  = (const float*)d_in[3];
    const float* ba  = (const float*)d_in[4];
    float* out = (float*)d_out;

    static bool attr_set = false;
    if (!attr_set){
        cudaFuncSetAttribute(k_out, cudaFuncAttributeMaxDynamicSharedMemorySize, K3_SMEM);
        cudaFuncSetAttribute(k_proj, cudaFuncAttributeMaxDynamicSharedMemorySize, P_SMEM);
        attr_set = true;
    }

    void* gp_addr = nullptr;
    cudaGetSymbolAddress(&gp_addr, g_p);
    cudaMemsetAsync(gp_addr, 0, sizeof(float)*NB*NL*NU);

    k_proj<<<dim3(16, KSPLIT), 256, P_SMEM>>>(inp, Wt);
    k_attn<<<dim3(NL/16, NB), 256>>>(bh, Wa, ba);
    k_out<<<dim3(NF/128, NL/128, NB), 256, K3_SMEM>>>(out);
}